// round 10
// baseline (speedup 1.0000x reference)
#include <cuda_runtime.h>
#include <math.h>

#define BC 48          // 16 batch * 3 channels
#define WS 11

typedef unsigned long long u64;

// ---- compile-time gaussian window (sigma=1.5, 11 taps, normalized) ---------
#define GW { 0.00102859f, 0.00759871f, 0.03600077f, 0.10936069f, 0.21300553f, \
             0.26601142f, 0.21300553f, 0.10936069f, 0.03600077f, 0.00759871f, \
             0.00102859f }

// ---------------- f32x2 packed-math helpers (sm_103a) ------------------------
__device__ __forceinline__ u64 pk2(float lo, float hi) {
    u64 r; asm("mov.b64 %0,{%1,%2};" : "=l"(r) : "f"(lo), "f"(hi)); return r;
}
__device__ __forceinline__ void up2(u64 v, float& a, float& b) {
    asm("mov.b64 {%0,%1},%2;" : "=f"(a), "=f"(b) : "l"(v));
}
__device__ __forceinline__ u64 fma2(u64 a, u64 b, u64 c) {
    u64 d; asm("fma.rn.f32x2 %0,%1,%2,%3;" : "=l"(d) : "l"(a), "l"(b), "l"(c)); return d;
}
__device__ __forceinline__ u64 mul2(u64 a, u64 b) {
    u64 d; asm("mul.rn.f32x2 %0,%1,%2;" : "=l"(d) : "l"(a), "l"(b)); return d;
}

// ---------------- device globals (scratch; no runtime allocation) -----------
__device__ double g_cs[5];
__device__ double g_ss[5];
// packed (u,v) pyramid ping-pong buffers
__device__ float2 g_uva[BC * 256 * 256];
__device__ float2 g_uvb[BC * 128 * 128];

// ---------------- init: zero accumulators -----------------------------------
__global__ void init_kernel() {
    if (threadIdx.x < 5) { g_cs[threadIdx.x] = 0.0; g_ss[threadIdx.x] = 0.0; }
}

// ---------------- fused: separable conv + SSIM stats + 2x2 pool -------------
// Rotated basis u=x+y, v=x-y. Pyramid levels >=1 store packed (u,v) float2.
// Filter packed (u,v) and (u^2,v^2). A=filt(u),B=filt(v),Qa=filt(u2),Qb=filt(v2):
//   2*s12+C2 = (da-db)/2+C2,  s1+s2+C2 = (da+db)/2+C2   (da=Qa-A^2, db=Qb-B^2)
//   2*mu1*mu2+C1 = (A^2-B^2)/2+C1,  mu1^2+mu2^2+C1 = (A^2+B^2)/2+C1
// Pooling is linear in (u,v): u' = Su/4, v' = Sv/4.
template<int TW, int TH, int NT, int HCW, bool PACKED>
__global__ __launch_bounds__(NT) void ssim_kernel(
    const float2* __restrict__ U,
    const float* __restrict__ X, const float* __restrict__ Y,
    float2* __restrict__ P,
    int H, int W, int level, int do_pool)
{
    constexpr int TIH = TH + 10, TIW = TW + 10;
    constexpr int TIW4 = (TIW + 3) & ~3;  // TIW rounded up to float4 multiple
    constexpr int PIN  = (TIW4 + 1) | 1;  // input pitch (float2 units), odd
    constexpr int PH   = TW + 1;          // h-array pitch (float4 units), odd
    constexpr int CG   = TW / HCW;        // h-pass column groups per row
    constexpr int RPT  = (TH * TW) / NT;  // output rows per thread in v-pass
    constexpr int NW   = NT / 32;

    __shared__ float2 s_in[TIH * PIN];    // packed (u,v)
    __shared__ float4 hm  [TIH * PH];     // (Gu,Gv,Gu2,Gv2)
    __shared__ double red0[NW], red1[NW];

    const int tid = threadIdx.x;
    const float wreg[WS] = GW;
    u64 wpk[WS];
    #pragma unroll
    for (int k = 0; k < WS; k++) wpk[k] = pk2(wreg[k], wreg[k]);

    const int img  = blockIdx.z;
    const int row0 = blockIdx.y * TH;
    const int col0 = blockIdx.x * TW;

    // ---- load input tile into s_in as (u,v) ----
    if (PACKED) {
        const float2* Ui = U + (size_t)img * H * W;
        constexpr int NCHP = (TIW + 1) / 2;   // float4 chunks (2 px each)
        if (row0 + TIH <= H && col0 + 2 * NCHP <= W) {
            for (int i = tid; i < TIH * NCHP; i += NT) {
                int r = i / NCHP, ch = i % NCHP;
                const float4 f = *(const float4*)&Ui[(size_t)(row0 + r) * W + col0 + 2 * ch];
                float2* dst = &s_in[r * PIN + 2 * ch];
                dst[0] = make_float2(f.x, f.y);
                dst[1] = make_float2(f.z, f.w);
            }
        } else {
            for (int i = tid; i < TIH * TIW; i += NT) {
                int r = i / TIW, c = i % TIW;
                int gr = row0 + r, gc = col0 + c;
                float2 uv = make_float2(0.f, 0.f);
                if (gr < H && gc < W) uv = Ui[(size_t)gr * W + gc];
                s_in[r * PIN + c] = uv;
            }
        }
    } else {
        const float* Xi = X + (size_t)img * H * W;
        const float* Yi = Y + (size_t)img * H * W;
        if (row0 + TIH <= H && col0 + TIW4 <= W) {
            constexpr int NCH = TIW4 / 4;
            for (int i = tid; i < TIH * NCH; i += NT) {
                int r = i / NCH, c4 = (i % NCH) * 4;
                const float4 xv = *(const float4*)&Xi[(size_t)(row0 + r) * W + col0 + c4];
                const float4 yv = *(const float4*)&Yi[(size_t)(row0 + r) * W + col0 + c4];
                float2* dst = &s_in[r * PIN + c4];
                dst[0] = make_float2(xv.x + yv.x, xv.x - yv.x);
                dst[1] = make_float2(xv.y + yv.y, xv.y - yv.y);
                dst[2] = make_float2(xv.z + yv.z, xv.z - yv.z);
                dst[3] = make_float2(xv.w + yv.w, xv.w - yv.w);
            }
        } else {
            for (int i = tid; i < TIH * TIW; i += NT) {
                int r = i / TIW, c = i % TIW;
                int gr = row0 + r, gc = col0 + c;
                float xv = 0.f, yv = 0.f;
                if (gr < H && gc < W) {
                    xv = Xi[(size_t)gr * W + gc];
                    yv = Yi[(size_t)gr * W + gc];
                }
                s_in[r * PIN + c] = make_float2(xv + yv, xv - yv);
            }
        }
    }
    __syncthreads();

    // ---- fused 2x2 avg pool (linear in u,v): u'=Su/4, v'=Sv/4 ----
    if (do_pool) {
        constexpr int PW = TW / 2, PHT = TH / 2;
        int Ho = H >> 1, Wo = W >> 1;
        for (int i = tid; i < PW * PHT; i += NT) {
            int pr = i / PW, pc = i % PW;
            float2 a = s_in[(2 * pr) * PIN + 2 * pc];
            float2 b = s_in[(2 * pr) * PIN + 2 * pc + 1];
            float2 c2 = s_in[(2 * pr + 1) * PIN + 2 * pc];
            float2 d = s_in[(2 * pr + 1) * PIN + 2 * pc + 1];
            float su = a.x + b.x + c2.x + d.x;
            float sv = a.y + b.y + c2.y + d.y;
            size_t o = (size_t)img * Ho * Wo + (size_t)((row0 >> 1) + pr) * Wo + (col0 >> 1) + pc;
            P[o] = make_float2(0.25f * su, 0.25f * sv);
        }
    }

    // ---- horizontal pass: HCW-column units, row-fastest (conflict-free) ----
    for (int u = tid; u < TIH * CG; u += NT) {
        int cgi = u / TIH;
        int r   = u - cgi * TIH;
        int cg  = cgi * HCW;
        const float2* prow = &s_in[r * PIN + cg];
        u64 m1[HCW], m2[HCW];
        #pragma unroll
        for (int j = 0; j < HCW; j++) { m1[j] = 0; m2[j] = 0; }
        #pragma unroll
        for (int i = 0; i < HCW + 10; i++) {
            float2 v = prow[i];
            u64 vp = pk2(v.x, v.y);
            u64 q  = mul2(vp, vp);
            #pragma unroll
            for (int j = 0; j < HCW; j++) {
                int t = i - j;
                if (t >= 0 && t < WS) {
                    m1[j] = fma2(wpk[t], vp, m1[j]);
                    m2[j] = fma2(wpk[t], q,  m2[j]);
                }
            }
        }
        int o = r * PH + cg;
        #pragma unroll
        for (int j = 0; j < HCW; j++) {
            float a, b, c, d;
            up2(m1[j], a, b);
            up2(m2[j], c, d);
            hm[o + j] = make_float4(a, b, c, d);
        }
    }
    __syncthreads();

    // ---- vertical pass + SSIM math (RPT rows per thread) ----
    const float C1 = 0.01f * 0.01f;
    const float C2 = 0.03f * 0.03f;
    const int c  = tid % TW;
    const int r0 = (tid / TW) * RPT;
    const int Hout = H - 10, Wout = W - 10;
    const bool colok = (col0 + c) < Wout;

    u64 a1[RPT], a2[RPT];
    #pragma unroll
    for (int j = 0; j < RPT; j++) { a1[j] = 0; a2[j] = 0; }

    const float4* pv = &hm[r0 * PH + c];
    #pragma unroll
    for (int k = 0; k < RPT + 10; k++) {
        float4 v = pv[k * PH];
        u64 p1 = pk2(v.x, v.y);
        u64 p2 = pk2(v.z, v.w);
        #pragma unroll
        for (int j = 0; j < RPT; j++) {
            int t = k - j;
            if (t >= 0 && t < WS) {
                a1[j] = fma2(wpk[t], p1, a1[j]);
                a2[j] = fma2(wpk[t], p2, a2[j]);
            }
        }
    }

    float cs_sum = 0.f, ss_sum = 0.f;
    #pragma unroll
    for (int j = 0; j < RPT; j++) {
        if (colok && (row0 + r0 + j) < Hout) {
            u64 sq = mul2(a1[j], a1[j]);     // (A^2, B^2)
            float A2, B2, Qa, Qb;
            up2(sq, A2, B2);
            up2(a2[j], Qa, Qb);
            float da = Qa - A2;
            float db = Qb - B2;
            float num  = 0.5f * (da - db) + C2;
            float den  = 0.5f * (da + db) + C2;
            float lnum = 0.5f * (A2 - B2) + C1;
            float lden = 0.5f * (A2 + B2) + C1;
            cs_sum += __fdividef(num, den);
            ss_sum += __fdividef(lnum * num, lden * den);
        }
    }

    // warp + block reduction
    #pragma unroll
    for (int o = 16; o > 0; o >>= 1) {
        cs_sum += __shfl_down_sync(0xffffffffu, cs_sum, o);
        ss_sum += __shfl_down_sync(0xffffffffu, ss_sum, o);
    }
    if ((tid & 31) == 0) { red0[tid >> 5] = cs_sum; red1[tid >> 5] = ss_sum; }
    __syncthreads();
    if (tid == 0) {
        double a = 0.0, b = 0.0;
        #pragma unroll
        for (int w = 0; w < NW; w++) { a += red0[w]; b += red1[w]; }
        atomicAdd(&g_cs[level], a);
        atomicAdd(&g_ss[level], b);
    }
}

// ---------------- final combine ----------------------------------------------
__global__ void finish_kernel(float* __restrict__ out)
{
    if (threadIdx.x != 0) return;
    const double w[5] = {0.0448, 0.2856, 0.3001, 0.2363, 0.1333};
    double ms = 1.0;
    #pragma unroll
    for (int l = 0; l < 5; l++) {
        int Hl = 512 >> l;
        double n  = 48.0 * (double)(Hl - 10) * (double)(Hl - 10);
        double cs = g_cs[l] / n; if (cs < 0.0) cs = 0.0; cs = (cs + 1.0) * 0.5;
        double ss = g_ss[l] / n; if (ss < 0.0) ss = 0.0; ss = (ss + 1.0) * 0.5;
        double v  = (l < 4) ? cs : ss;
        ms *= pow(v, w[l]);
    }
    out[0] = (float)(1.0 - ms);
}

// ---------------- host launch -------------------------------------------------
static inline dim3 conv_grid(int H, int W, int tw, int th) {
    int Hout = H - 10, Wout = W - 10;
    return dim3((Wout + tw - 1) / tw, (Hout + th - 1) / th, BC);
}

extern "C" void kernel_launch(void* const* d_in, const int* in_sizes, int n_in,
                              void* d_out, int out_size)
{
    const float* X0 = (const float*)d_in[0];
    const float* Y0 = (const float*)d_in[1];
    float* out = (float*)d_out;

    float2 *uva, *uvb;
    cudaGetSymbolAddress((void**)&uva, g_uva);
    cudaGetSymbolAddress((void**)&uvb, g_uvb);

    init_kernel<<<1, 32>>>();

    // level 0: 512 (raw x,y) -> pool into uva (256, packed uv)
    ssim_kernel<32, 32, 256, 4, false><<<conv_grid(512, 512, 32, 32), 256>>>(
        nullptr, X0, Y0, uva, 512, 512, 0, 1);
    // level 1: 256 -> pool into uvb (128)
    ssim_kernel<32, 32, 256, 4, true><<<conv_grid(256, 256, 32, 32), 256>>>(
        uva, nullptr, nullptr, uvb, 256, 256, 1, 1);
    // level 2: 128 -> pool into uva (64)
    ssim_kernel<32, 32, 256, 4, true><<<conv_grid(128, 128, 32, 32), 256>>>(
        uvb, nullptr, nullptr, uva, 128, 128, 2, 1);
    // level 3: 64 -> pool into uvb (32)  (256-thread small tiles: short critical path)
    ssim_kernel<16, 16, 256, 4, true><<<conv_grid(64, 64, 16, 16), 256>>>(
        uva, nullptr, nullptr, uvb, 64, 64, 3, 1);
    // level 4: 32, no pool
    ssim_kernel<16, 16, 256, 4, true><<<conv_grid(32, 32, 16, 16), 256>>>(
        uvb, nullptr, nullptr, nullptr, 32, 32, 4, 0);

    finish_kernel<<<1, 32>>>(out);
}

// round 11
// speedup vs baseline: 1.0573x; 1.0573x over previous
#include <cuda_runtime.h>
#include <math.h>

#define BC 48          // 16 batch * 3 channels
#define WS 11

typedef unsigned long long u64;

// ---- compile-time gaussian window (sigma=1.5, 11 taps, normalized) ---------
#define GW { 0.00102859f, 0.00759871f, 0.03600077f, 0.10936069f, 0.21300553f, \
             0.26601142f, 0.21300553f, 0.10936069f, 0.03600077f, 0.00759871f, \
             0.00102859f }

// ---------------- f32x2 packed-math helpers (sm_103a) ------------------------
__device__ __forceinline__ u64 pk2(float lo, float hi) {
    u64 r; asm("mov.b64 %0,{%1,%2};" : "=l"(r) : "f"(lo), "f"(hi)); return r;
}
__device__ __forceinline__ void up2(u64 v, float& a, float& b) {
    asm("mov.b64 {%0,%1},%2;" : "=f"(a), "=f"(b) : "l"(v));
}
__device__ __forceinline__ u64 fma2(u64 a, u64 b, u64 c) {
    u64 d; asm("fma.rn.f32x2 %0,%1,%2,%3;" : "=l"(d) : "l"(a), "l"(b), "l"(c)); return d;
}
__device__ __forceinline__ u64 mul2(u64 a, u64 b) {
    u64 d; asm("mul.rn.f32x2 %0,%1,%2;" : "=l"(d) : "l"(a), "l"(b)); return d;
}

// ---------------- device globals (scratch; no runtime allocation) -----------
__device__ double g_cs[5];      // zero-init; self-cleaned by final block
__device__ double g_ss[5];
__device__ int    g_tick;       // zero-init; self-cleaned
__device__ float g_xa[BC * 256 * 256];
__device__ float g_ya[BC * 256 * 256];
__device__ float g_xb[BC * 128 * 128];
__device__ float g_yb[BC * 128 * 128];

// ---------------- fused: separable conv + SSIM stats + 2x2 pool -------------
// Rotated basis u=x+y, v=x-y. Filter only packed (u,v) and (u^2,v^2).
// A=filt(u),B=filt(v),Qa=filt(u2),Qb=filt(v2); da=Qa-A^2, db=Qb-B^2:
//   2*s12+C2 = (da-db)/2+C2,  s1+s2+C2 = (da+db)/2+C2
//   2*mu1*mu2+C1 = (A^2-B^2)/2+C1,  mu1^2+mu2^2+C1 = (A^2+B^2)/2+C1
// FINAL: last finishing block computes the MS-SSIM combine, writes out[0],
// and resets all accumulators (self-cleaning for graph replay).
template<int TW, int TH, int NT, int HCW, bool FINAL>
__global__ __launch_bounds__(NT) void ssim_kernel(
    const float* __restrict__ X, const float* __restrict__ Y,
    float* __restrict__ XP, float* __restrict__ YP,
    int H, int W, int level, int do_pool, float* __restrict__ out)
{
    constexpr int TIH = TH + 10, TIW = TW + 10;
    constexpr int TIW4 = (TIW + 3) & ~3;  // TIW rounded up to float4 multiple
    constexpr int PIN  = (TIW4 + 1) | 1;  // input pitch (float2 units), odd
    constexpr int PH   = TW + 1;          // h-array pitch (float4 units), odd
    constexpr int CG   = TW / HCW;        // h-pass column groups per row
    constexpr int RPT  = (TH * TW) / NT;  // output rows per thread in v-pass
    constexpr int NW   = NT / 32;

    __shared__ float2 s_in[TIH * PIN];    // packed (u,v)
    __shared__ float4 hm  [TIH * PH];     // (Gu,Gv,Gu2,Gv2)
    __shared__ double red0[NW], red1[NW];

    const int tid = threadIdx.x;
    const float wreg[WS] = GW;
    u64 wpk[WS];
    #pragma unroll
    for (int k = 0; k < WS; k++) wpk[k] = pk2(wreg[k], wreg[k]);

    const int img  = blockIdx.z;
    const float* Xi = X + (size_t)img * H * W;
    const float* Yi = Y + (size_t)img * H * W;
    const int row0 = blockIdx.y * TH;
    const int col0 = blockIdx.x * TW;

    // ---- load input tile, rotate to (u,v) = (x+y, x-y) ----
    if (row0 + TIH <= H && col0 + TIW4 <= W) {
        constexpr int NCH = TIW4 / 4;     // float4 chunks per row
        for (int i = tid; i < TIH * NCH; i += NT) {
            int r = i / NCH, c4 = (i % NCH) * 4;
            const float4 xv = *(const float4*)&Xi[(size_t)(row0 + r) * W + col0 + c4];
            const float4 yv = *(const float4*)&Yi[(size_t)(row0 + r) * W + col0 + c4];
            float2* dst = &s_in[r * PIN + c4];
            dst[0] = make_float2(xv.x + yv.x, xv.x - yv.x);
            dst[1] = make_float2(xv.y + yv.y, xv.y - yv.y);
            dst[2] = make_float2(xv.z + yv.z, xv.z - yv.z);
            dst[3] = make_float2(xv.w + yv.w, xv.w - yv.w);
        }
    } else {
        for (int i = tid; i < TIH * TIW; i += NT) {
            int r = i / TIW, c = i % TIW;
            int gr = row0 + r, gc = col0 + c;
            float xv = 0.f, yv = 0.f;
            if (gr < H && gc < W) {
                xv = Xi[(size_t)gr * W + gc];
                yv = Yi[(size_t)gr * W + gc];
            }
            s_in[r * PIN + c] = make_float2(xv + yv, xv - yv);
        }
    }
    __syncthreads();

    // ---- fused 2x2 avg pool: x=(u+v)/2, y=(u-v)/2 -> xp=(Su+Sv)/8 ----
    if (do_pool) {
        constexpr int PW = TW / 2, PHT = TH / 2;
        int Ho = H >> 1, Wo = W >> 1;
        for (int i = tid; i < PW * PHT; i += NT) {
            int pr = i / PW, pc = i % PW;
            float2 a = s_in[(2 * pr) * PIN + 2 * pc];
            float2 b = s_in[(2 * pr) * PIN + 2 * pc + 1];
            float2 c2 = s_in[(2 * pr + 1) * PIN + 2 * pc];
            float2 d = s_in[(2 * pr + 1) * PIN + 2 * pc + 1];
            float su = a.x + b.x + c2.x + d.x;
            float sv = a.y + b.y + c2.y + d.y;
            size_t o = (size_t)img * Ho * Wo + (size_t)((row0 >> 1) + pr) * Wo + (col0 >> 1) + pc;
            XP[o] = 0.125f * (su + sv);
            YP[o] = 0.125f * (su - sv);
        }
    }

    // ---- horizontal pass: HCW-column units, row-fastest (conflict-free) ----
    for (int u = tid; u < TIH * CG; u += NT) {
        int cgi = u / TIH;
        int r   = u - cgi * TIH;
        int cg  = cgi * HCW;
        const float2* prow = &s_in[r * PIN + cg];
        u64 m1[HCW], m2[HCW];
        #pragma unroll
        for (int j = 0; j < HCW; j++) { m1[j] = 0; m2[j] = 0; }
        #pragma unroll
        for (int i = 0; i < HCW + 10; i++) {
            float2 v = prow[i];
            u64 vp = pk2(v.x, v.y);
            u64 q  = mul2(vp, vp);
            #pragma unroll
            for (int j = 0; j < HCW; j++) {
                int t = i - j;
                if (t >= 0 && t < WS) {
                    m1[j] = fma2(wpk[t], vp, m1[j]);
                    m2[j] = fma2(wpk[t], q,  m2[j]);
                }
            }
        }
        int o = r * PH + cg;
        #pragma unroll
        for (int j = 0; j < HCW; j++) {
            float a, b, c, d;
            up2(m1[j], a, b);
            up2(m2[j], c, d);
            hm[o + j] = make_float4(a, b, c, d);
        }
    }
    __syncthreads();

    // ---- vertical pass + SSIM math (RPT rows per thread) ----
    const float C1 = 0.01f * 0.01f;
    const float C2 = 0.03f * 0.03f;
    const int c  = tid % TW;
    const int r0 = (tid / TW) * RPT;
    const int Hout = H - 10, Wout = W - 10;
    const bool colok = (col0 + c) < Wout;

    u64 a1[RPT], a2[RPT];
    #pragma unroll
    for (int j = 0; j < RPT; j++) { a1[j] = 0; a2[j] = 0; }

    const float4* pv = &hm[r0 * PH + c];
    #pragma unroll
    for (int k = 0; k < RPT + 10; k++) {
        float4 v = pv[k * PH];
        u64 p1 = pk2(v.x, v.y);
        u64 p2 = pk2(v.z, v.w);
        #pragma unroll
        for (int j = 0; j < RPT; j++) {
            int t = k - j;
            if (t >= 0 && t < WS) {
                a1[j] = fma2(wpk[t], p1, a1[j]);
                a2[j] = fma2(wpk[t], p2, a2[j]);
            }
        }
    }

    float cs_sum = 0.f, ss_sum = 0.f;
    #pragma unroll
    for (int j = 0; j < RPT; j++) {
        if (colok && (row0 + r0 + j) < Hout) {
            u64 sq = mul2(a1[j], a1[j]);     // (A^2, B^2)
            float A2, B2, Qa, Qb;
            up2(sq, A2, B2);
            up2(a2[j], Qa, Qb);
            float da = Qa - A2;
            float db = Qb - B2;
            float num  = 0.5f * (da - db) + C2;
            float den  = 0.5f * (da + db) + C2;
            float lnum = 0.5f * (A2 - B2) + C1;
            float lden = 0.5f * (A2 + B2) + C1;
            cs_sum += __fdividef(num, den);
            ss_sum += __fdividef(lnum * num, lden * den);
        }
    }

    // warp + block reduction
    #pragma unroll
    for (int o = 16; o > 0; o >>= 1) {
        cs_sum += __shfl_down_sync(0xffffffffu, cs_sum, o);
        ss_sum += __shfl_down_sync(0xffffffffu, ss_sum, o);
    }
    if ((tid & 31) == 0) { red0[tid >> 5] = cs_sum; red1[tid >> 5] = ss_sum; }
    __syncthreads();
    if (tid == 0) {
        double a = 0.0, b = 0.0;
        #pragma unroll
        for (int w = 0; w < NW; w++) { a += red0[w]; b += red1[w]; }
        atomicAdd(&g_cs[level], a);
        atomicAdd(&g_ss[level], b);

        if (FINAL) {
            __threadfence();
            int nblk = gridDim.x * gridDim.y * gridDim.z;
            int t = atomicAdd(&g_tick, 1);
            if (t == nblk - 1) {
                __threadfence();
                const double w[5] = {0.0448, 0.2856, 0.3001, 0.2363, 0.1333};
                double ms = 1.0;
                #pragma unroll
                for (int l = 0; l < 5; l++) {
                    int Hl = 512 >> l;
                    double n  = 48.0 * (double)(Hl - 10) * (double)(Hl - 10);
                    double cs = g_cs[l] / n; if (cs < 0.0) cs = 0.0; cs = (cs + 1.0) * 0.5;
                    double ss = g_ss[l] / n; if (ss < 0.0) ss = 0.0; ss = (ss + 1.0) * 0.5;
                    double v  = (l < 4) ? cs : ss;
                    ms *= pow(v, w[l]);
                }
                out[0] = (float)(1.0 - ms);
                // self-clean for next graph replay
                #pragma unroll
                for (int l = 0; l < 5; l++) { g_cs[l] = 0.0; g_ss[l] = 0.0; }
                g_tick = 0;
            }
        }
    }
}

// ---------------- host launch -------------------------------------------------
static inline dim3 conv_grid(int H, int W, int tw, int th) {
    int Hout = H - 10, Wout = W - 10;
    return dim3((Wout + tw - 1) / tw, (Hout + th - 1) / th, BC);
}

extern "C" void kernel_launch(void* const* d_in, const int* in_sizes, int n_in,
                              void* d_out, int out_size)
{
    const float* X0 = (const float*)d_in[0];
    const float* Y0 = (const float*)d_in[1];
    float* out = (float*)d_out;

    float *xa, *ya, *xb, *yb;
    cudaGetSymbolAddress((void**)&xa, g_xa);
    cudaGetSymbolAddress((void**)&ya, g_ya);
    cudaGetSymbolAddress((void**)&xb, g_xb);
    cudaGetSymbolAddress((void**)&yb, g_yb);

    // level 0: 512 -> pool into xa/ya (256)
    ssim_kernel<32, 32, 256, 4, false><<<conv_grid(512, 512, 32, 32), 256>>>(
        X0, Y0, xa, ya, 512, 512, 0, 1, nullptr);
    // level 1: 256 -> pool into xb/yb (128)
    ssim_kernel<32, 32, 256, 4, false><<<conv_grid(256, 256, 32, 32), 256>>>(
        xa, ya, xb, yb, 256, 256, 1, 1, nullptr);
    // level 2: 128 -> pool into xa/ya (64)
    ssim_kernel<32, 32, 256, 4, false><<<conv_grid(128, 128, 32, 32), 256>>>(
        xb, yb, xa, ya, 128, 128, 2, 1, nullptr);
    // level 3: 64 -> pool into xb/yb (32)   (256-thread small tiles: short path)
    ssim_kernel<16, 16, 256, 4, false><<<conv_grid(64, 64, 16, 16), 256>>>(
        xa, ya, xb, yb, 64, 64, 3, 1, nullptr);
    // level 4: 32, no pool; last block computes final combine + self-clean
    ssim_kernel<16, 16, 256, 4, true><<<conv_grid(32, 32, 16, 16), 256>>>(
        xb, yb, nullptr, nullptr, 32, 32, 4, 0, out);
}